// round 2
// baseline (speedup 1.0000x reference)
#include <cuda_runtime.h>
#include <math.h>

// ---------------------------------------------------------------------------
// TPAttention: x@Wq/Wk/Wv -> RoPE -> GQA flash attention over KV cache -> @Wo
// Shapes: B=8 S=4 P=4096 HID=4096 HQ=32 HKV=8 D=128  (M = B*S = 32)
// ---------------------------------------------------------------------------

namespace {
constexpr int cB = 8, cS = 4, cP = 4096, cHQ = 32, cHKV = 8, cD = 128;
constexpr int cM = cB * cS;             // 32
constexpr int cK = 4096;                // hidden dim (GEMM K)
constexpr int cNQ = cHQ * cD;           // 4096
constexpr int cNKV = cHKV * cD;         // 1024
constexpr int cNTOT = cNQ + 2 * cNKV;   // 6144
constexpr int cT = cP + cS;             // 4100 total keys
constexpr int KSPLIT = 4;               // split-K for GEMMs
constexpr int KCHUNK = cK / KSPLIT;     // 1024
constexpr int NSPLIT = 4;               // flash-decoding KV splits
constexpr int KBLK = 64;                // keys per inner tile
constexpr int NKB = (cT + KBLK - 1) / KBLK;        // 65
constexpr int KBPS = (NKB + NSPLIT - 1) / NSPLIT;  // 17
// smem: qs[16*128] ks[64*132] vs[64*132] ps[16*68] mrun/lrun/fac[16 each]
constexpr int ATTN_SMEM = (16 * 128 + 2 * 64 * 132 + 16 * 68 + 48) * 4;
}  // namespace

__device__ float g_qkvp[KSPLIT][cM * cNTOT];        // split-K partials of qkv
__device__ float g_q[cM * cHQ * cD];                // q after rope  [b][s][hq][d]
__device__ float g_kn[cM * cHKV * cD];              // new k (rope)  [b][s][hk][d]
__device__ float g_vn[cM * cHKV * cD];              // new v         [b][s][hk][d]
__device__ float g_Op[cB * cHKV * NSPLIT * 16 * cD];// partial O per split
__device__ float g_Ms[cB * cHKV * NSPLIT * 16];     // running max per split
__device__ float g_Ls[cB * cHKV * NSPLIT * 16];     // running sum per split
__device__ float g_ao[cM * cNQ];                    // attention output [m][hq*d]
__device__ float g_outp[KSPLIT][cM * cNQ];          // split-K partials of out

// ---------------------------------------------------------------------------
// GEMM: C_split = A[32 x 4096] @ W[k-range x N], register tiled 4x4,
// 64-col N tiles, split-K over grid.y, plain stores into per-split buffers.
// ---------------------------------------------------------------------------
__global__ __launch_bounds__(128) void gemm32_kernel(
    const float* __restrict__ A, const float* __restrict__ W,
    float* __restrict__ Cb, int ldw, int ldc, int csz) {
  __shared__ float xs[16][36];   // [kk][m], padded: aligned float4 rows
  __shared__ float ws[16][64];   // [kk][n]
  const int tid = threadIdx.x;
  const int mg = tid >> 4;       // 0..7  -> rows 4*mg..+3
  const int ng = tid & 15;       // 0..15 -> cols 4*ng..+3
  const int n0 = blockIdx.x * 64;
  const int k0s = blockIdx.y * KCHUNK;
  float* C = Cb + blockIdx.y * csz;

  const int lm = tid >> 2;       // x-load: row 0..31
  const int lkv = tid & 3;       // x-load: float4 idx in k-chunk
  const int wk0 = tid >> 4;      // w-load: kk 0..7 (+8 for second)
  const int wn0 = tid & 15;      // w-load: float4 col

  float acc[4][4];
#pragma unroll
  for (int i = 0; i < 4; i++)
#pragma unroll
    for (int j = 0; j < 4; j++) acc[i][j] = 0.f;

  float4 xr = *(const float4*)&A[lm * cK + k0s + 4 * lkv];
  float4 wr0 = *(const float4*)&W[(k0s + wk0) * ldw + n0 + 4 * wn0];
  float4 wr1 = *(const float4*)&W[(k0s + wk0 + 8) * ldw + n0 + 4 * wn0];

  for (int k0 = k0s; k0 < k0s + KCHUNK; k0 += 16) {
    __syncthreads();
    xs[4 * lkv + 0][lm] = xr.x;
    xs[4 * lkv + 1][lm] = xr.y;
    xs[4 * lkv + 2][lm] = xr.z;
    xs[4 * lkv + 3][lm] = xr.w;
    *(float4*)&ws[wk0][4 * wn0] = wr0;
    *(float4*)&ws[wk0 + 8][4 * wn0] = wr1;
    __syncthreads();
    if (k0 + 16 < k0s + KCHUNK) {
      const int k1 = k0 + 16;
      xr = *(const float4*)&A[lm * cK + k1 + 4 * lkv];
      wr0 = *(const float4*)&W[(k1 + wk0) * ldw + n0 + 4 * wn0];
      wr1 = *(const float4*)&W[(k1 + wk0 + 8) * ldw + n0 + 4 * wn0];
    }
#pragma unroll
    for (int kk = 0; kk < 16; kk++) {
      float4 xv = *(const float4*)&xs[kk][4 * mg];
      float4 wv = *(const float4*)&ws[kk][4 * ng];
      float xa[4] = {xv.x, xv.y, xv.z, xv.w};
      float wa[4] = {wv.x, wv.y, wv.z, wv.w};
#pragma unroll
      for (int i = 0; i < 4; i++)
#pragma unroll
        for (int j = 0; j < 4; j++) acc[i][j] = fmaf(xa[i], wa[j], acc[i][j]);
    }
  }
#pragma unroll
  for (int i = 0; i < 4; i++) {
    const int m = mg * 4 + i;
#pragma unroll
    for (int j = 0; j < 4; j++) C[m * ldc + n0 + 4 * ng + j] = acc[i][j];
  }
}

// ---------------------------------------------------------------------------
// Reduce split-K partials of qkv, apply RoPE to q/k, scatter to buffers.
// ---------------------------------------------------------------------------
__global__ __launch_bounds__(256) void rope_kernel(
    const float* __restrict__ cosb, const float* __restrict__ sinb,
    const int* __restrict__ past_len) {
  const int i = blockIdx.x * 256 + threadIdx.x;
  if (i >= cM * cNTOT) return;
  const int m = i / cNTOT, c = i - m * cNTOT;
  const int s = m & 3;
  const float val = g_qkvp[0][i] + g_qkvp[1][i] + g_qkvp[2][i] + g_qkvp[3][i];
  const int pos = past_len[0] + s;
  if (c < cNQ) {
    const int hq = c >> 7, d = c & 127;
    const int io = m * cNTOT + (c ^ 64);  // rope partner (d +/- 64)
    const float oth = g_qkvp[0][io] + g_qkvp[1][io] + g_qkvp[2][io] + g_qkvp[3][io];
    const float rot = (d < 64) ? -oth : oth;
    g_q[(m * cHQ + hq) * cD + d] =
        fmaf(val, cosb[pos * cD + d], rot * sinb[pos * cD + d]);
  } else if (c < cNQ + cNKV) {
    const int cc = c - cNQ;
    const int hk = cc >> 7, d = cc & 127;
    const int io = m * cNTOT + cNQ + (cc ^ 64);
    const float oth = g_qkvp[0][io] + g_qkvp[1][io] + g_qkvp[2][io] + g_qkvp[3][io];
    const float rot = (d < 64) ? -oth : oth;
    g_kn[(m * cHKV + hk) * cD + d] =
        fmaf(val, cosb[pos * cD + d], rot * sinb[pos * cD + d]);
  } else {
    const int cc = c - cNQ - cNKV;
    g_vn[(m * cHKV + (cc >> 7)) * cD + (cc & 127)] = val;
  }
}

// ---------------------------------------------------------------------------
// Flash-decoding attention. Grid (b*hkv=64, NSPLIT=4), 128 threads.
// 16 query rows (s*4+g) per block share the kv head. Online softmax.
// ---------------------------------------------------------------------------
__global__ __launch_bounds__(128) void attn_kernel(
    const float* __restrict__ kc, const float* __restrict__ vc,
    const int* __restrict__ past_len) {
  extern __shared__ float sm[];
  float* qs = sm;               // [16][128]
  float* ks = qs + 16 * 128;    // [64][132]  (padded, float4-aligned rows)
  float* vs = ks + 64 * 132;    // [64][132]
  float* ps = vs + 64 * 132;    // [16][68]
  float* mrun = ps + 16 * 68;   // [16]
  float* lrun = mrun + 16;      // [16]
  float* fac = lrun + 16;       // [16]

  const int tid = threadIdx.x;
  const int bh = blockIdx.x;
  const int b = bh >> 3, h = bh & 7;
  const int split = blockIdx.y;
  const int pl = past_len[0];
  const float scale = 0.08838834764831845f;  // 1/sqrt(128)

#pragma unroll
  for (int it = 0; it < 4; it++) {
    const int idx = tid + it * 128;  // 0..511
    const int r = idx >> 5, dv = idx & 31;
    const int s = r >> 2, g = r & 3;
    float4 qv = *(const float4*)&g_q[((b * cS + s) * cHQ + (h * 4 + g)) * cD + 4 * dv];
    qv.x *= scale; qv.y *= scale; qv.z *= scale; qv.w *= scale;
    *(float4*)&qs[r * 128 + 4 * dv] = qv;
  }
  if (tid < 16) { mrun[tid] = -1e30f; lrun[tid] = 0.f; }

  const int rg = tid >> 4;   // score phase: rows 2rg, 2rg+1
  const int kg = tid & 15;   // score phase: keys kg + 16*i
  const int vrg = tid >> 5;  // pv phase: rows 4vrg..+3
  const int dg = tid & 31;   // pv phase: d = 4*dg

  float4 o4[4];
#pragma unroll
  for (int j = 0; j < 4; j++) o4[j] = make_float4(0.f, 0.f, 0.f, 0.f);

  const int kb0 = split * KBPS;
  const int kb1 = (kb0 + KBPS < NKB) ? (kb0 + KBPS) : NKB;
  for (int kb = kb0; kb < kb1; kb++) {
    const int t0 = kb * KBLK;
    __syncthreads();
#pragma unroll
    for (int it = 0; it < 16; it++) {
      const int idx = tid + it * 128;  // 0..2047
      const int tt = idx >> 5, dv = idx & 31;
      const int t = t0 + tt;
      float4 kv, vv;
      if (t < cP) {
        const int off = ((b * cP + t) * cHKV + h) * cD + 4 * dv;
        kv = *(const float4*)&kc[off];
        vv = *(const float4*)&vc[off];
      } else if (t < cT) {
        const int off = ((b * cS + (t - cP)) * cHKV + h) * cD + 4 * dv;
        kv = *(const float4*)&g_kn[off];
        vv = *(const float4*)&g_vn[off];
      } else {
        kv = make_float4(0.f, 0.f, 0.f, 0.f);
        vv = kv;
      }
      *(float4*)&ks[tt * 132 + 4 * dv] = kv;
      *(float4*)&vs[tt * 132 + 4 * dv] = vv;
    }
    __syncthreads();

    // ---- scores: 2 rows x 4 keys per thread ----
    float sc[2][4];
#pragma unroll
    for (int rr = 0; rr < 2; rr++)
#pragma unroll
      for (int i = 0; i < 4; i++) sc[rr][i] = 0.f;
#pragma unroll 8
    for (int dv = 0; dv < 32; dv++) {
      const float4 q0 = *(const float4*)&qs[(2 * rg) * 128 + 4 * dv];
      const float4 q1 = *(const float4*)&qs[(2 * rg + 1) * 128 + 4 * dv];
#pragma unroll
      for (int i = 0; i < 4; i++) {
        const float4 kv = *(const float4*)&ks[(kg + 16 * i) * 132 + 4 * dv];
        sc[0][i] = fmaf(q0.x, kv.x, fmaf(q0.y, kv.y, fmaf(q0.z, kv.z, fmaf(q0.w, kv.w, sc[0][i]))));
        sc[1][i] = fmaf(q1.x, kv.x, fmaf(q1.y, kv.y, fmaf(q1.z, kv.z, fmaf(q1.w, kv.w, sc[1][i]))));
      }
    }
#pragma unroll
    for (int rr = 0; rr < 2; rr++) {
      const int r = 2 * rg + rr;
      const int s = r >> 2;
      float mx = -1e30f;
#pragma unroll
      for (int i = 0; i < 4; i++) {
        const int t = t0 + kg + 16 * i;
        if (t > pl + s) sc[rr][i] = -1e30f;  // causal mask (+ tail)
        mx = fmaxf(mx, sc[rr][i]);
      }
#pragma unroll
      for (int w = 8; w; w >>= 1) mx = fmaxf(mx, __shfl_xor_sync(0xffffffffu, mx, w));
      const float mold = mrun[r];
      const float mnew = fmaxf(mold, mx);
      const float f = __expf(mold - mnew);
      float lsum = 0.f;
#pragma unroll
      for (int i = 0; i < 4; i++) {
        const float p = __expf(sc[rr][i] - mnew);
        ps[r * 68 + kg + 16 * i] = p;
        lsum += p;
      }
#pragma unroll
      for (int w = 8; w; w >>= 1) lsum += __shfl_xor_sync(0xffffffffu, lsum, w);
      if (kg == 0) {
        mrun[r] = mnew;
        lrun[r] = fmaf(lrun[r], f, lsum);
        fac[r] = f;
      }
    }
    __syncthreads();

    // ---- P @ V: 4 rows x float4(d) per thread ----
    float fr[4];
#pragma unroll
    for (int j = 0; j < 4; j++) fr[j] = fac[4 * vrg + j];
#pragma unroll
    for (int j = 0; j < 4; j++) {
      o4[j].x *= fr[j]; o4[j].y *= fr[j]; o4[j].z *= fr[j]; o4[j].w *= fr[j];
    }
#pragma unroll 8
    for (int tt = 0; tt < KBLK; tt++) {
      const float4 vv = *(const float4*)&vs[tt * 132 + 4 * dg];
#pragma unroll
      for (int j = 0; j < 4; j++) {
        const float p = ps[(4 * vrg + j) * 68 + tt];
        o4[j].x = fmaf(p, vv.x, o4[j].x);
        o4[j].y = fmaf(p, vv.y, o4[j].y);
        o4[j].z = fmaf(p, vv.z, o4[j].z);
        o4[j].w = fmaf(p, vv.w, o4[j].w);
      }
    }
  }
  __syncthreads();
  const int base = (bh * NSPLIT + split) * 16;
#pragma unroll
  for (int j = 0; j < 4; j++) {
    const int r = 4 * vrg + j;
    *(float4*)&g_Op[(base + r) * cD + 4 * dg] = o4[j];
  }
  if (tid < 16) {
    g_Ms[base + tid] = mrun[tid];
    g_Ls[base + tid] = lrun[tid];
  }
}

// ---------------------------------------------------------------------------
// Combine KV splits (flash-decoding reduction) -> attention output buffer.
// ---------------------------------------------------------------------------
__global__ __launch_bounds__(256) void combine_kernel() {
  const int bh = blockIdx.x, tid = threadIdx.x;
  const int r = tid >> 4;
  const int dq = (tid & 15) * 8;
  const int b = bh >> 3, h = bh & 7;
  const int base = bh * NSPLIT;
  float m[NSPLIT], l[NSPLIT];
  float mstar = -1e30f;
#pragma unroll
  for (int i = 0; i < NSPLIT; i++) {
    m[i] = g_Ms[(base + i) * 16 + r];
    l[i] = g_Ls[(base + i) * 16 + r];
    mstar = fmaxf(mstar, m[i]);
  }
  float w[NSPLIT];
  float L = 0.f;
#pragma unroll
  for (int i = 0; i < NSPLIT; i++) {
    w[i] = __expf(m[i] - mstar);
    L = fmaf(w[i], l[i], L);
  }
  const float inv = 1.f / L;
  const int s = r >> 2, g = r & 3;
  float* dst = &g_ao[((b * cS + s) * cHQ + (h * 4 + g)) * cD + dq];
#pragma unroll
  for (int c2 = 0; c2 < 2; c2++) {
    float4 a = make_float4(0.f, 0.f, 0.f, 0.f);
#pragma unroll
    for (int i = 0; i < NSPLIT; i++) {
      const float4 ov = *(const float4*)&g_Op[((base + i) * 16 + r) * cD + dq + 4 * c2];
      a.x = fmaf(w[i], ov.x, a.x);
      a.y = fmaf(w[i], ov.y, a.y);
      a.z = fmaf(w[i], ov.z, a.z);
      a.w = fmaf(w[i], ov.w, a.w);
    }
    a.x *= inv; a.y *= inv; a.z *= inv; a.w *= inv;
    *(float4*)&dst[4 * c2] = a;
  }
}

// ---------------------------------------------------------------------------
// Reduce split-K partials of the output projection into d_out.
// ---------------------------------------------------------------------------
__global__ __launch_bounds__(256) void sum_out_kernel(float* __restrict__ out) {
  const int i = blockIdx.x * 256 + threadIdx.x;
  if (i < cM * cNQ)
    out[i] = g_outp[0][i] + g_outp[1][i] + g_outp[2][i] + g_outp[3][i];
}

// ---------------------------------------------------------------------------
extern "C" void kernel_launch(void* const* d_in, const int* in_sizes, int n_in,
                              void* d_out, int out_size) {
  const float* x = (const float*)d_in[0];
  const float* wq = (const float*)d_in[1];
  const float* wk = (const float*)d_in[2];
  const float* wv = (const float*)d_in[3];
  const float* wo = (const float*)d_in[4];
  const float* cosb = (const float*)d_in[5];
  const float* sinb = (const float*)d_in[6];
  const float* kc = (const float*)d_in[7];
  const float* vc = (const float*)d_in[8];
  const int* pl = (const int*)d_in[9];
  float* out = (float*)d_out;

  float *qkvp, *aop, *outp;
  cudaGetSymbolAddress((void**)&qkvp, g_qkvp);
  cudaGetSymbolAddress((void**)&aop, g_ao);
  cudaGetSymbolAddress((void**)&outp, g_outp);

  // QKV projections (split-K partials)
  gemm32_kernel<<<dim3(cNQ / 64, KSPLIT), 128>>>(x, wq, qkvp, cNQ, cNTOT, cM * cNTOT);
  gemm32_kernel<<<dim3(cNKV / 64, KSPLIT), 128>>>(x, wk, qkvp + cNQ, cNKV, cNTOT, cM * cNTOT);
  gemm32_kernel<<<dim3(cNKV / 64, KSPLIT), 128>>>(x, wv, qkvp + cNQ + cNKV, cNKV, cNTOT, cM * cNTOT);
  // reduce + RoPE
  rope_kernel<<<(cM * cNTOT + 255) / 256, 256>>>(cosb, sinb, pl);
  // flash-decoding attention
  cudaFuncSetAttribute(attn_kernel, cudaFuncAttributeMaxDynamicSharedMemorySize, ATTN_SMEM);
  attn_kernel<<<dim3(cB * cHKV, NSPLIT), 128, ATTN_SMEM>>>(kc, vc, pl);
  combine_kernel<<<cB * cHKV, 256>>>();
  // output projection
  gemm32_kernel<<<dim3(cNQ / 64, KSPLIT), 128>>>(aop, wo, outp, cNQ, cNQ, cM * cNQ);
  sum_out_kernel<<<(cM * cNQ + 255) / 256, 256>>>(out);
}

// round 3
// speedup vs baseline: 1.3529x; 1.3529x over previous
#include <cuda_runtime.h>
#include <math.h>

// ---------------------------------------------------------------------------
// TPAttention: x@Wq/Wk/Wv -> RoPE -> GQA flash attention over KV cache -> @Wo
// Shapes: B=8 S=4 P=4096 HID=4096 HQ=32 HKV=8 D=128  (M = B*S = 32)
// fp32 math throughout, packed via f32x2 (FFMA2) for 2x FMA throughput.
// ---------------------------------------------------------------------------

namespace {
constexpr int cB = 8, cS = 4, cP = 4096, cHQ = 32, cHKV = 8, cD = 128;
constexpr int cM = cB * cS;             // 32
constexpr int cK = 4096;                // hidden dim (GEMM K)
constexpr int cNQ = cHQ * cD;           // 4096
constexpr int cNKV = cHKV * cD;         // 1024
constexpr int cNTOT = cNQ + 2 * cNKV;   // 6144
constexpr int cT = cP + cS;             // 4100 total keys
constexpr int KSPLIT = 4;               // split-K for GEMMs
constexpr int KCHUNK = cK / KSPLIT;     // 1024
constexpr int NSPLIT = 4;               // flash-decoding KV splits
constexpr int KBLK = 64;                // keys per inner tile
constexpr int NKB = (cT + KBLK - 1) / KBLK;        // 65
constexpr int KBPS = (NKB + NSPLIT - 1) / NSPLIT;  // 17
constexpr int ATTN_SMEM = (16 * 128 + 2 * 64 * 132 + 16 * 68) * 4;
}  // namespace

typedef unsigned long long ull;

__device__ __forceinline__ ull pack2(float lo, float hi) {
  ull r;
  asm("mov.b64 %0, {%1, %2};" : "=l"(r) : "f"(lo), "f"(hi));
  return r;
}
__device__ __forceinline__ float2 unpack2(ull v) {
  float2 f;
  asm("mov.b64 {%0, %1}, %2;" : "=f"(f.x), "=f"(f.y) : "l"(v));
  return f;
}
__device__ __forceinline__ void ffma2(ull& d, ull a, ull b) {
  asm("fma.rn.f32x2 %0, %1, %2, %0;" : "+l"(d) : "l"(a), "l"(b));
}
__device__ __forceinline__ ull fmul2(ull a, ull b) {
  ull r;
  asm("mul.rn.f32x2 %0, %1, %2;" : "=l"(r) : "l"(a), "l"(b));
  return r;
}

__device__ float g_qkvp[KSPLIT][cM * cNTOT];        // split-K partials of qkv
__device__ float g_q[cM * cHQ * cD];                // q after rope
__device__ float g_kn[cM * cHKV * cD];              // new k (rope)
__device__ float g_vn[cM * cHKV * cD];              // new v
__device__ float g_Op[cB * cHKV * NSPLIT * 16 * cD];// partial O per split
__device__ float g_Ms[cB * cHKV * NSPLIT * 16];     // running max per split
__device__ float g_Ls[cB * cHKV * NSPLIT * 16];     // running sum per split
__device__ float g_ao[cM * cNQ];                    // attention output
__device__ float g_outp[KSPLIT][cM * cNQ];          // split-K partials of out

// ---------------------------------------------------------------------------
// GEMM (f32x2): C_split = A[32 x 4096] @ W, 64-col N tiles, split-K grid.y.
// qkv mode: blockIdx.x selects among {Wq (64 tiles), Wk (16), Wv (16)}.
// 128 threads: mg=tid>>4 (4 m rows), ng=tid&15 (4 n cols as 2 f32x2 pairs).
// One __syncthreads per 16-k tile via register-staged double buffer.
// ---------------------------------------------------------------------------
__global__ __launch_bounds__(128) void gemm_f2_kernel(
    const float* __restrict__ A, const float* __restrict__ W0,
    const float* __restrict__ W1, const float* __restrict__ W2,
    float* __restrict__ Cb, int qkv) {
  __shared__ float xs[2][16][36];
  __shared__ float ws[2][16][68];
  const int tid = threadIdx.x;
  const int bx = blockIdx.x;

  const float* W;
  int ldw, ncol, ldc, csz;
  if (qkv) {
    ldc = cNTOT; csz = cM * cNTOT;
    if (bx < 64)      { W = W0; ldw = cNQ;  ncol = bx * 64; }
    else if (bx < 80) { W = W1; ldw = cNKV; ncol = cNQ + (bx - 64) * 64; }
    else              { W = W2; ldw = cNKV; ncol = cNQ + cNKV + (bx - 80) * 64; }
  } else {
    ldc = cNQ; csz = cM * cNQ;
    W = W0; ldw = cNQ; ncol = bx * 64;
  }
  const int n0w = (qkv ? (ncol - (bx < 64 ? 0 : (bx < 80 ? cNQ : cNQ + cNKV)))
                       : ncol);
  const int k0s = blockIdx.y * KCHUNK;
  float* C = Cb + blockIdx.y * csz;

  const int mg = tid >> 4;   // 0..7
  const int ng = tid & 15;   // 0..15
  const int lm = tid >> 2;   // x-load row 0..31
  const int lkv = tid & 3;   // x-load float4 idx
  const int wk0 = tid >> 4;  // w-load kk 0..7 (+8)
  const int wn = tid & 15;   // w-load float4 col
  const int wgcol = n0w + 4 * wn;

  ull acc[4][2] = {};

  float4 xr = *(const float4*)&A[lm * cK + k0s + 4 * lkv];
  float4 wr0 = *(const float4*)&W[(k0s + wk0) * ldw + wgcol];
  float4 wr1 = *(const float4*)&W[(k0s + wk0 + 8) * ldw + wgcol];
  xs[0][4 * lkv + 0][lm] = xr.x;
  xs[0][4 * lkv + 1][lm] = xr.y;
  xs[0][4 * lkv + 2][lm] = xr.z;
  xs[0][4 * lkv + 3][lm] = xr.w;
  *(float4*)&ws[0][wk0][4 * wn] = wr0;
  *(float4*)&ws[0][wk0 + 8][4 * wn] = wr1;
  __syncthreads();

  const int NT = KCHUNK / 16;  // 64
  for (int t = 0; t < NT; t++) {
    const int st = t & 1;
    const bool more = (t + 1 < NT);
    if (more) {
      const int k1 = k0s + 16 * (t + 1);
      xr = *(const float4*)&A[lm * cK + k1 + 4 * lkv];
      wr0 = *(const float4*)&W[(k1 + wk0) * ldw + wgcol];
      wr1 = *(const float4*)&W[(k1 + wk0 + 8) * ldw + wgcol];
    }
#pragma unroll
    for (int kk = 0; kk < 16; kk++) {
      const float4 xv = *(const float4*)&xs[st][kk][4 * mg];
      const ulonglong2 wv = *(const ulonglong2*)&ws[st][kk][4 * ng];
      const ull x0 = pack2(xv.x, xv.x);
      const ull x1 = pack2(xv.y, xv.y);
      const ull x2 = pack2(xv.z, xv.z);
      const ull x3 = pack2(xv.w, xv.w);
      ffma2(acc[0][0], x0, wv.x); ffma2(acc[0][1], x0, wv.y);
      ffma2(acc[1][0], x1, wv.x); ffma2(acc[1][1], x1, wv.y);
      ffma2(acc[2][0], x2, wv.x); ffma2(acc[2][1], x2, wv.y);
      ffma2(acc[3][0], x3, wv.x); ffma2(acc[3][1], x3, wv.y);
    }
    if (more) {
      const int s2 = st ^ 1;
      xs[s2][4 * lkv + 0][lm] = xr.x;
      xs[s2][4 * lkv + 1][lm] = xr.y;
      xs[s2][4 * lkv + 2][lm] = xr.z;
      xs[s2][4 * lkv + 3][lm] = xr.w;
      *(float4*)&ws[s2][wk0][4 * wn] = wr0;
      *(float4*)&ws[s2][wk0 + 8][4 * wn] = wr1;
    }
    __syncthreads();
  }

#pragma unroll
  for (int i = 0; i < 4; i++) {
    const float2 lo = unpack2(acc[i][0]);
    const float2 hi = unpack2(acc[i][1]);
    float4 o = make_float4(lo.x, lo.y, hi.x, hi.y);
    *(float4*)&C[(4 * mg + i) * ldc + ncol + 4 * ng] = o;
  }
}

// ---------------------------------------------------------------------------
// Reduce split-K partials of qkv, apply RoPE to q/k, scatter to buffers.
// ---------------------------------------------------------------------------
__global__ __launch_bounds__(256) void rope_kernel(
    const float* __restrict__ cosb, const float* __restrict__ sinb,
    const int* __restrict__ past_len) {
  const int i = blockIdx.x * 256 + threadIdx.x;
  if (i >= cM * cNTOT) return;
  const int m = i / cNTOT, c = i - m * cNTOT;
  const int s = m & 3;
  const float val = g_qkvp[0][i] + g_qkvp[1][i] + g_qkvp[2][i] + g_qkvp[3][i];
  const int pos = past_len[0] + s;
  if (c < cNQ) {
    const int hq = c >> 7, d = c & 127;
    const int io = m * cNTOT + (c ^ 64);
    const float oth = g_qkvp[0][io] + g_qkvp[1][io] + g_qkvp[2][io] + g_qkvp[3][io];
    const float rot = (d < 64) ? -oth : oth;
    g_q[(m * cHQ + hq) * cD + d] =
        fmaf(val, cosb[pos * cD + d], rot * sinb[pos * cD + d]);
  } else if (c < cNQ + cNKV) {
    const int cc = c - cNQ;
    const int hk = cc >> 7, d = cc & 127;
    const int io = m * cNTOT + cNQ + (cc ^ 64);
    const float oth = g_qkvp[0][io] + g_qkvp[1][io] + g_qkvp[2][io] + g_qkvp[3][io];
    const float rot = (d < 64) ? -oth : oth;
    g_kn[(m * cHKV + hk) * cD + d] =
        fmaf(val, cosb[pos * cD + d], rot * sinb[pos * cD + d]);
  } else {
    const int cc = c - cNQ - cNKV;
    g_vn[(m * cHKV + (cc >> 7)) * cD + (cc & 127)] = val;
  }
}

// ---------------------------------------------------------------------------
// Flash-decoding attention. Grid (b*hkv=64, NSPLIT=4), 128 threads = 4 warps.
// Warp rg owns rows 4rg..4rg+3 (s=rg); lanes own keys kg,kg+32 in scores and
// d-chunk 4kg..4kg+3 in PV. Softmax state entirely in registers.
// ---------------------------------------------------------------------------
__global__ __launch_bounds__(128) void attn_kernel(
    const float* __restrict__ kc, const float* __restrict__ vc,
    const int* __restrict__ past_len) {
  extern __shared__ float sm[];
  float* qs = sm;               // [16][128]
  float* ks = qs + 16 * 128;    // [64][132]
  float* vs = ks + 64 * 132;    // [64][132]
  float* ps = vs + 64 * 132;    // [16][68]

  const int tid = threadIdx.x;
  const int bh = blockIdx.x;
  const int b = bh >> 3, h = bh & 7;
  const int split = blockIdx.y;
  const int pl = past_len[0];
  const float scale = 0.08838834764831845f;  // 1/sqrt(128)
  const int rg = tid >> 5;   // warp id = row group (s index)
  const int kg = tid & 31;   // key lane / d lane

#pragma unroll
  for (int it = 0; it < 4; it++) {
    const int idx = tid + it * 128;  // 0..511
    const int r = idx >> 5, dv = idx & 31;
    const int s = r >> 2, g = r & 3;
    float4 qv = *(const float4*)&g_q[((b * cS + s) * cHQ + (h * 4 + g)) * cD + 4 * dv];
    qv.x *= scale; qv.y *= scale; qv.z *= scale; qv.w *= scale;
    *(float4*)&qs[r * 128 + 4 * dv] = qv;
  }

  float mrun[4] = {-1e30f, -1e30f, -1e30f, -1e30f};
  float lrun[4] = {0.f, 0.f, 0.f, 0.f};
  ull o2[4][2] = {};

  const int kb0 = split * KBPS;
  const int kb1 = (kb0 + KBPS < NKB) ? (kb0 + KBPS) : NKB;
  for (int kb = kb0; kb < kb1; kb++) {
    const int t0 = kb * KBLK;
    __syncthreads();
#pragma unroll
    for (int it = 0; it < 16; it++) {
      const int idx = tid + it * 128;  // 0..2047
      const int tt = idx >> 5, dv = idx & 31;
      const int t = t0 + tt;
      float4 kv, vv;
      if (t < cP) {
        const int off = ((b * cP + t) * cHKV + h) * cD + 4 * dv;
        kv = *(const float4*)&kc[off];
        vv = *(const float4*)&vc[off];
      } else if (t < cT) {
        const int off = ((b * cS + (t - cP)) * cHKV + h) * cD + 4 * dv;
        kv = *(const float4*)&g_kn[off];
        vv = *(const float4*)&g_vn[off];
      } else {
        kv = make_float4(0.f, 0.f, 0.f, 0.f);
        vv = kv;
      }
      *(float4*)&ks[tt * 132 + 4 * dv] = kv;
      *(float4*)&vs[tt * 132 + 4 * dv] = vv;
    }
    __syncthreads();

    // ---- scores: 4 rows x 2 keys (kg, kg+32) per thread, f32x2 packed ----
    ull sc2[4][2] = {};
#pragma unroll 8
    for (int dv = 0; dv < 32; dv++) {
      const ulonglong2 k0v = *(const ulonglong2*)&ks[kg * 132 + 4 * dv];
      const ulonglong2 k1v = *(const ulonglong2*)&ks[(kg + 32) * 132 + 4 * dv];
#pragma unroll
      for (int j = 0; j < 4; j++) {
        const ulonglong2 qv = *(const ulonglong2*)&qs[(4 * rg + j) * 128 + 4 * dv];
        ffma2(sc2[j][0], qv.x, k0v.x); ffma2(sc2[j][0], qv.y, k0v.y);
        ffma2(sc2[j][1], qv.x, k1v.x); ffma2(sc2[j][1], qv.y, k1v.y);
      }
    }

    float fac[4];
#pragma unroll
    for (int j = 0; j < 4; j++) {
      const float2 a = unpack2(sc2[j][0]);
      const float2 c = unpack2(sc2[j][1]);
      float s0 = a.x + a.y;
      float s1 = c.x + c.y;
      if (t0 + kg > pl + rg) s0 = -1e30f;        // causal + tail mask
      if (t0 + kg + 32 > pl + rg) s1 = -1e30f;
      float mx = fmaxf(s0, s1);
#pragma unroll
      for (int w = 16; w; w >>= 1) mx = fmaxf(mx, __shfl_xor_sync(0xffffffffu, mx, w));
      const float mnew = fmaxf(mrun[j], mx);
      const float f = __expf(mrun[j] - mnew);
      const float p0 = (s0 < -1e29f) ? 0.f : __expf(s0 - mnew);
      const float p1 = (s1 < -1e29f) ? 0.f : __expf(s1 - mnew);
      ps[(4 * rg + j) * 68 + kg] = p0;
      ps[(4 * rg + j) * 68 + kg + 32] = p1;
      float ls = p0 + p1;
#pragma unroll
      for (int w = 16; w; w >>= 1) ls += __shfl_xor_sync(0xffffffffu, ls, w);
      lrun[j] = fmaf(lrun[j], f, ls);
      mrun[j] = mnew;
      fac[j] = f;
    }
    __syncwarp();

    // ---- P @ V: 4 rows x f32x2[2] (d-chunk 4kg..4kg+3) per thread ----
#pragma unroll
    for (int j = 0; j < 4; j++) {
      const ull ff = pack2(fac[j], fac[j]);
      o2[j][0] = fmul2(o2[j][0], ff);
      o2[j][1] = fmul2(o2[j][1], ff);
    }
#pragma unroll 4
    for (int tt = 0; tt < KBLK; tt += 4) {
      float4 p4[4];
#pragma unroll
      for (int j = 0; j < 4; j++)
        p4[j] = *(const float4*)&ps[(4 * rg + j) * 68 + tt];
#pragma unroll
      for (int u = 0; u < 4; u++) {
        const ulonglong2 vv = *(const ulonglong2*)&vs[(tt + u) * 132 + 4 * kg];
#pragma unroll
        for (int j = 0; j < 4; j++) {
          const float p = (&p4[j].x)[u];
          const ull pp = pack2(p, p);
          ffma2(o2[j][0], pp, vv.x);
          ffma2(o2[j][1], pp, vv.y);
        }
      }
    }
  }

  const int base = (bh * NSPLIT + split) * 16;
#pragma unroll
  for (int j = 0; j < 4; j++) {
    const int r = 4 * rg + j;
    const float2 lo = unpack2(o2[j][0]);
    const float2 hi = unpack2(o2[j][1]);
    float4 o = make_float4(lo.x, lo.y, hi.x, hi.y);
    *(float4*)&g_Op[(base + r) * cD + 4 * kg] = o;
  }
  if (kg == 0) {
#pragma unroll
    for (int j = 0; j < 4; j++) {
      g_Ms[base + 4 * rg + j] = mrun[j];
      g_Ls[base + 4 * rg + j] = lrun[j];
    }
  }
}

// ---------------------------------------------------------------------------
// Combine KV splits (flash-decoding reduction) -> attention output buffer.
// ---------------------------------------------------------------------------
__global__ __launch_bounds__(256) void combine_kernel() {
  const int bh = blockIdx.x, tid = threadIdx.x;
  const int r = tid >> 4;
  const int dq = (tid & 15) * 8;
  const int b = bh >> 3, h = bh & 7;
  const int base = bh * NSPLIT;
  float m[NSPLIT], l[NSPLIT];
  float mstar = -1e30f;
#pragma unroll
  for (int i = 0; i < NSPLIT; i++) {
    m[i] = g_Ms[(base + i) * 16 + r];
    l[i] = g_Ls[(base + i) * 16 + r];
    mstar = fmaxf(mstar, m[i]);
  }
  float w[NSPLIT];
  float L = 0.f;
#pragma unroll
  for (int i = 0; i < NSPLIT; i++) {
    w[i] = __expf(m[i] - mstar);
    L = fmaf(w[i], l[i], L);
  }
  const float inv = 1.f / L;
  const int s = r >> 2, g = r & 3;
  float* dst = &g_ao[((b * cS + s) * cHQ + (h * 4 + g)) * cD + dq];
#pragma unroll
  for (int c2 = 0; c2 < 2; c2++) {
    float4 a = make_float4(0.f, 0.f, 0.f, 0.f);
#pragma unroll
    for (int i = 0; i < NSPLIT; i++) {
      const float4 ov = *(const float4*)&g_Op[((base + i) * 16 + r) * cD + dq + 4 * c2];
      a.x = fmaf(w[i], ov.x, a.x);
      a.y = fmaf(w[i], ov.y, a.y);
      a.z = fmaf(w[i], ov.z, a.z);
      a.w = fmaf(w[i], ov.w, a.w);
    }
    a.x *= inv; a.y *= inv; a.z *= inv; a.w *= inv;
    *(float4*)&dst[4 * c2] = a;
  }
}

// ---------------------------------------------------------------------------
// Reduce split-K partials of the output projection into d_out.
// ---------------------------------------------------------------------------
__global__ __launch_bounds__(256) void sum_out_kernel(float* __restrict__ out) {
  const int i = blockIdx.x * 256 + threadIdx.x;
  if (i < cM * cNQ)
    out[i] = g_outp[0][i] + g_outp[1][i] + g_outp[2][i] + g_outp[3][i];
}

// ---------------------------------------------------------------------------
extern "C" void kernel_launch(void* const* d_in, const int* in_sizes, int n_in,
                              void* d_out, int out_size) {
  const float* x = (const float*)d_in[0];
  const float* wq = (const float*)d_in[1];
  const float* wk = (const float*)d_in[2];
  const float* wv = (const float*)d_in[3];
  const float* wo = (const float*)d_in[4];
  const float* cosb = (const float*)d_in[5];
  const float* sinb = (const float*)d_in[6];
  const float* kc = (const float*)d_in[7];
  const float* vc = (const float*)d_in[8];
  const int* pl = (const int*)d_in[9];
  float* out = (float*)d_out;

  float *qkvp, *aop, *outp;
  cudaGetSymbolAddress((void**)&qkvp, g_qkvp);
  cudaGetSymbolAddress((void**)&aop, g_ao);
  cudaGetSymbolAddress((void**)&outp, g_outp);

  // Combined QKV projection (split-K partials): 64 q-tiles + 16 k + 16 v
  gemm_f2_kernel<<<dim3(96, KSPLIT), 128>>>(x, wq, wk, wv, qkvp, 1);
  // reduce + RoPE
  rope_kernel<<<(cM * cNTOT + 255) / 256, 256>>>(cosb, sinb, pl);
  // flash-decoding attention
  cudaFuncSetAttribute(attn_kernel, cudaFuncAttributeMaxDynamicSharedMemorySize, ATTN_SMEM);
  attn_kernel<<<dim3(cB * cHKV, NSPLIT), 128, ATTN_SMEM>>>(kc, vc, pl);
  combine_kernel<<<cB * cHKV, 256>>>();
  // output projection
  gemm_f2_kernel<<<dim3(64, KSPLIT), 128>>>(aop, wo, wo, wo, outp, 0);
  sum_out_kernel<<<(cM * cNQ + 255) / 256, 256>>>(out);
}

// round 4
// speedup vs baseline: 1.8895x; 1.3966x over previous
#include <cuda_runtime.h>
#include <math.h>
#include <stdint.h>

// ---------------------------------------------------------------------------
// TPAttention: x@Wq/Wk/Wv -> RoPE -> GQA flash attention over KV cache -> @Wo
// B=8 S=4 P=4096 HID=4096 HQ=32 HKV=8 D=128 (M=32). fp32 math, f32x2 FMA.
// ---------------------------------------------------------------------------

namespace {
constexpr int cB = 8, cS = 4, cP = 4096, cHQ = 32, cHKV = 8, cD = 128;
constexpr int cM = cB * cS;             // 32
constexpr int cK = 4096;
constexpr int cNQ = cHQ * cD;           // 4096
constexpr int cNKV = cHKV * cD;         // 1024
constexpr int cNTOT = cNQ + 2 * cNKV;   // 6144
constexpr int cT = cP + cS;             // 4100
constexpr int KSPLIT = 4;
constexpr int KCHUNK = cK / KSPLIT;     // 1024
constexpr int NSPLIT = 4;               // flash-decoding KV splits
constexpr int KBLK = 32;                // keys per tile (cp.async stage)
constexpr int NKB = (cT + KBLK - 1) / KBLK;        // 129
constexpr int KBPS = (NKB + NSPLIT - 1) / NSPLIT;  // 33
// smem: qs[16*128] + ks[2][32*132] + vs[2][32*132] + ps[16*36]
constexpr int ATTN_SMEM = (16 * 128 + 4 * 32 * 132 + 16 * 36) * 4;  // 78080
}  // namespace

typedef unsigned long long ull;

__device__ __forceinline__ ull pack2(float lo, float hi) {
  ull r;
  asm("mov.b64 %0, {%1, %2};" : "=l"(r) : "f"(lo), "f"(hi));
  return r;
}
__device__ __forceinline__ float2 unpack2(ull v) {
  float2 f;
  asm("mov.b64 {%0, %1}, %2;" : "=f"(f.x), "=f"(f.y) : "l"(v));
  return f;
}
__device__ __forceinline__ void ffma2(ull& d, ull a, ull b) {
  asm("fma.rn.f32x2 %0, %1, %2, %0;" : "+l"(d) : "l"(a), "l"(b));
}
__device__ __forceinline__ ull fmul2(ull a, ull b) {
  ull r;
  asm("mul.rn.f32x2 %0, %1, %2;" : "=l"(r) : "l"(a), "l"(b));
  return r;
}
__device__ __forceinline__ void cpa16(uint32_t s, const void* g) {
  asm volatile("cp.async.cg.shared.global [%0], [%1], 16;" :: "r"(s), "l"(g));
}
__device__ __forceinline__ void cpa_commit() {
  asm volatile("cp.async.commit_group;");
}
template <int N>
__device__ __forceinline__ void cpa_wait() {
  asm volatile("cp.async.wait_group %0;" :: "n"(N));
}

__device__ float g_qkvp[KSPLIT][cM * cNTOT];
__device__ float g_q[cM * cHQ * cD];
__device__ float g_kn[cM * cHKV * cD];
__device__ float g_vn[cM * cHKV * cD];
__device__ float g_Op[cB * cHKV * NSPLIT * 16 * cD];
__device__ float g_Ms[cB * cHKV * NSPLIT * 16];
__device__ float g_Ls[cB * cHKV * NSPLIT * 16];
__device__ float g_ao[cM * cNQ];
__device__ float g_outp[KSPLIT][cM * cNQ];

// ---------------------------------------------------------------------------
// GEMM (f32x2): C_split = A[32 x 4096] @ W, 64-col N tiles, split-K grid.y.
// k-step 32 (512 compute cycles per prefetch batch), double-buffered smem.
// ---------------------------------------------------------------------------
__global__ __launch_bounds__(128) void gemm_f2_kernel(
    const float* __restrict__ A, const float* __restrict__ W0,
    const float* __restrict__ W1, const float* __restrict__ W2,
    float* __restrict__ Cb, int qkv) {
  __shared__ float xs[2][32][36];
  __shared__ float ws[2][32][68];
  const int tid = threadIdx.x;
  const int bx = blockIdx.x;

  const float* W;
  int ldw, ncol, ldc, csz;
  if (qkv) {
    ldc = cNTOT; csz = cM * cNTOT;
    if (bx < 64)      { W = W0; ldw = cNQ;  ncol = bx * 64; }
    else if (bx < 80) { W = W1; ldw = cNKV; ncol = cNQ + (bx - 64) * 64; }
    else              { W = W2; ldw = cNKV; ncol = cNQ + cNKV + (bx - 80) * 64; }
  } else {
    ldc = cNQ; csz = cM * cNQ;
    W = W0; ldw = cNQ; ncol = bx * 64;
  }
  const int n0w = (qkv ? (ncol - (bx < 64 ? 0 : (bx < 80 ? cNQ : cNQ + cNKV)))
                       : ncol);
  const int k0s = blockIdx.y * KCHUNK;
  float* C = Cb + blockIdx.y * csz;

  const int mg = tid >> 4;   // 0..7
  const int ng = tid & 15;   // 0..15
  const int lm = tid >> 2;   // x-load row 0..31
  const int lkv = tid & 3;   // x-load float4 idx (k 4lkv, 16+4lkv)
  const int wk0 = tid >> 4;  // w-load kk 0..7 (+8,+16,+24)
  const int wn = tid & 15;
  const int wgcol = n0w + 4 * wn;

  ull acc[4][2] = {};

  float4 xr0 = *(const float4*)&A[lm * cK + k0s + 4 * lkv];
  float4 xr1 = *(const float4*)&A[lm * cK + k0s + 16 + 4 * lkv];
  float4 wr[4];
#pragma unroll
  for (int q = 0; q < 4; q++)
    wr[q] = *(const float4*)&W[(k0s + wk0 + 8 * q) * ldw + wgcol];

#pragma unroll
  for (int c = 0; c < 4; c++) {
    xs[0][4 * lkv + c][lm] = (&xr0.x)[c];
    xs[0][16 + 4 * lkv + c][lm] = (&xr1.x)[c];
  }
#pragma unroll
  for (int q = 0; q < 4; q++) *(float4*)&ws[0][wk0 + 8 * q][4 * wn] = wr[q];
  __syncthreads();

  const int NT = KCHUNK / 32;  // 32
  for (int t = 0; t < NT; t++) {
    const int st = t & 1;
    const bool more = (t + 1 < NT);
    if (more) {
      const int k1 = k0s + 32 * (t + 1);
      xr0 = *(const float4*)&A[lm * cK + k1 + 4 * lkv];
      xr1 = *(const float4*)&A[lm * cK + k1 + 16 + 4 * lkv];
#pragma unroll
      for (int q = 0; q < 4; q++)
        wr[q] = *(const float4*)&W[(k1 + wk0 + 8 * q) * ldw + wgcol];
    }
#pragma unroll
    for (int kk = 0; kk < 32; kk++) {
      const float4 xv = *(const float4*)&xs[st][kk][4 * mg];
      const ulonglong2 wv = *(const ulonglong2*)&ws[st][kk][4 * ng];
      const ull x0 = pack2(xv.x, xv.x);
      const ull x1 = pack2(xv.y, xv.y);
      const ull x2 = pack2(xv.z, xv.z);
      const ull x3 = pack2(xv.w, xv.w);
      ffma2(acc[0][0], x0, wv.x); ffma2(acc[0][1], x0, wv.y);
      ffma2(acc[1][0], x1, wv.x); ffma2(acc[1][1], x1, wv.y);
      ffma2(acc[2][0], x2, wv.x); ffma2(acc[2][1], x2, wv.y);
      ffma2(acc[3][0], x3, wv.x); ffma2(acc[3][1], x3, wv.y);
    }
    if (more) {
      const int s2 = st ^ 1;
#pragma unroll
      for (int c = 0; c < 4; c++) {
        xs[s2][4 * lkv + c][lm] = (&xr0.x)[c];
        xs[s2][16 + 4 * lkv + c][lm] = (&xr1.x)[c];
      }
#pragma unroll
      for (int q = 0; q < 4; q++) *(float4*)&ws[s2][wk0 + 8 * q][4 * wn] = wr[q];
    }
    __syncthreads();
  }

#pragma unroll
  for (int i = 0; i < 4; i++) {
    const float2 lo = unpack2(acc[i][0]);
    const float2 hi = unpack2(acc[i][1]);
    float4 o = make_float4(lo.x, lo.y, hi.x, hi.y);
    *(float4*)&C[(4 * mg + i) * ldc + ncol + 4 * ng] = o;
  }
}

// ---------------------------------------------------------------------------
// Reduce split-K partials of qkv, apply RoPE to q/k, scatter to buffers.
// ---------------------------------------------------------------------------
__global__ __launch_bounds__(256) void rope_kernel(
    const float* __restrict__ cosb, const float* __restrict__ sinb,
    const int* __restrict__ past_len) {
  const int i = blockIdx.x * 256 + threadIdx.x;
  if (i >= cM * cNTOT) return;
  const int m = i / cNTOT, c = i - m * cNTOT;
  const int s = m & 3;
  const float val = g_qkvp[0][i] + g_qkvp[1][i] + g_qkvp[2][i] + g_qkvp[3][i];
  const int pos = past_len[0] + s;
  if (c < cNQ) {
    const int hq = c >> 7, d = c & 127;
    const int io = m * cNTOT + (c ^ 64);
    const float oth = g_qkvp[0][io] + g_qkvp[1][io] + g_qkvp[2][io] + g_qkvp[3][io];
    const float rot = (d < 64) ? -oth : oth;
    g_q[(m * cHQ + hq) * cD + d] =
        fmaf(val, cosb[pos * cD + d], rot * sinb[pos * cD + d]);
  } else if (c < cNQ + cNKV) {
    const int cc = c - cNQ;
    const int hk = cc >> 7, d = cc & 127;
    const int io = m * cNTOT + cNQ + (cc ^ 64);
    const float oth = g_qkvp[0][io] + g_qkvp[1][io] + g_qkvp[2][io] + g_qkvp[3][io];
    const float rot = (d < 64) ? -oth : oth;
    g_kn[(m * cHKV + hk) * cD + d] =
        fmaf(val, cosb[pos * cD + d], rot * sinb[pos * cD + d]);
  } else {
    const int cc = c - cNQ - cNKV;
    g_vn[(m * cHKV + (cc >> 7)) * cD + (cc & 127)] = val;
  }
}

// ---------------------------------------------------------------------------
// Flash-decoding attention, cp.async double-buffered K/V (KBLK=32, 2 stages).
// Grid (64 bh, NSPLIT). 128 threads = 4 warps; warp rg owns rows 4rg..4rg+3.
// Score: lane = key. PV: lane = d-chunk (float4). Softmax state in regs.
// ---------------------------------------------------------------------------
__global__ __launch_bounds__(128) void attn_kernel(
    const float* __restrict__ kc, const float* __restrict__ vc,
    const int* __restrict__ past_len) {
  extern __shared__ float sm[];
  float* qs = sm;                    // [16][128]
  float* ks = qs + 16 * 128;         // [2][32][132]
  float* vs = ks + 2 * 32 * 132;     // [2][32][132]
  float* ps = vs + 2 * 32 * 132;     // [16][36]

  const int tid = threadIdx.x;
  const int bh = blockIdx.x;
  const int b = bh >> 3, h = bh & 7;
  const int split = blockIdx.y;
  const int pl = past_len[0];
  const float scale = 0.08838834764831845f;  // 1/sqrt(128)
  const int rg = tid >> 5;   // warp id = s index
  const int kg = tid & 31;   // key lane / d lane

  // per-thread cp.async coordinates: two (tt,dv) slots per stage fill pass
  const int tta = tid >> 4;          // 0..7   (slot A rows, with +8/+16/+24)
  const int dva = tid & 15;          // paired below

#pragma unroll
  for (int it = 0; it < 4; it++) {
    const int idx = tid + it * 128;
    const int r = idx >> 5, dv = idx & 31;
    const int s = r >> 2, g = r & 3;
    float4 qv = *(const float4*)&g_q[((b * cS + s) * cHQ + (h * 4 + g)) * cD + 4 * dv];
    qv.x *= scale; qv.y *= scale; qv.z *= scale; qv.w *= scale;
    *(float4*)&qs[r * 128 + 4 * dv] = qv;
  }

  const uint32_t ks_base = (uint32_t)__cvta_generic_to_shared(ks);
  const uint32_t vs_base = (uint32_t)__cvta_generic_to_shared(vs);

  const int kb0 = split * KBPS;
  const int kb1 = (kb0 + KBPS < NKB) ? (kb0 + KBPS) : NKB;
  const int ntiles = kb1 - kb0;

  // issue cp.async for one tile into stage st
  auto load_tile = [&](int kb, int st) {
    const int t0 = kb * KBLK;
    const uint32_t kdst0 = ks_base + (uint32_t)(st * 32 * 132 * 4);
    const uint32_t vdst0 = vs_base + (uint32_t)(st * 32 * 132 * 4);
#pragma unroll
    for (int it = 0; it < 8; it++) {
      const int idx = tid + it * 128;       // 0..1023
      const int tt = idx >> 5, dv = idx & 31;
      int t = t0 + tt;
      if (t > cT - 1) t = cT - 1;           // clamp tail (finite data; masked)
      const float *ksrc, *vsrc;
      if (t < cP) {
        const int off = ((b * cP + t) * cHKV + h) * cD + 4 * dv;
        ksrc = kc + off; vsrc = vc + off;
      } else {
        const int off = ((b * cS + (t - cP)) * cHKV + h) * cD + 4 * dv;
        ksrc = g_kn + off; vsrc = g_vn + off;
      }
      const uint32_t so = (uint32_t)((tt * 132 + 4 * dv) * 4);
      cpa16(kdst0 + so, ksrc);
      cpa16(vdst0 + so, vsrc);
    }
  };

  float mrun[4] = {-1e30f, -1e30f, -1e30f, -1e30f};
  float lrun[4] = {0.f, 0.f, 0.f, 0.f};
  ull o2[4][2] = {};

  load_tile(kb0, 0);
  cpa_commit();

  for (int i = 0; i < ntiles; i++) {
    const int st = i & 1;
    const int t0 = (kb0 + i) * KBLK;
    const bool more = (i + 1 < ntiles);
    if (more) {
      load_tile(kb0 + i + 1, st ^ 1);
      cpa_commit();
      cpa_wait<1>();
    } else {
      cpa_wait<0>();
    }
    __syncthreads();

    const float* kst = ks + st * 32 * 132;
    const float* vst = vs + st * 32 * 132;

    // ---- scores: 4 rows x 1 key (lane) per thread, 2 chains per row ----
    ull sa[4] = {}, sb[4] = {};
#pragma unroll 8
    for (int dv = 0; dv < 32; dv++) {
      const ulonglong2 kv = *(const ulonglong2*)&kst[kg * 132 + 4 * dv];
#pragma unroll
      for (int j = 0; j < 4; j++) {
        const ulonglong2 qv = *(const ulonglong2*)&qs[(4 * rg + j) * 128 + 4 * dv];
        ffma2(sa[j], qv.x, kv.x);
        ffma2(sb[j], qv.y, kv.y);
      }
    }

    float fac[4];
#pragma unroll
    for (int j = 0; j < 4; j++) {
      const float2 a = unpack2(sa[j]);
      const float2 c = unpack2(sb[j]);
      float s0 = (a.x + a.y) + (c.x + c.y);
      if (t0 + kg > pl + rg) s0 = -1e30f;   // causal + tail mask
      float mx = s0;
#pragma unroll
      for (int w = 16; w; w >>= 1) mx = fmaxf(mx, __shfl_xor_sync(0xffffffffu, mx, w));
      const float mnew = fmaxf(mrun[j], mx);
      const float f = __expf(mrun[j] - mnew);
      const float p0 = (s0 < -1e29f) ? 0.f : __expf(s0 - mnew);
      ps[(4 * rg + j) * 36 + kg] = p0;
      float ls = p0;
#pragma unroll
      for (int w = 16; w; w >>= 1) ls += __shfl_xor_sync(0xffffffffu, ls, w);
      lrun[j] = fmaf(lrun[j], f, ls);
      mrun[j] = mnew;
      fac[j] = f;
    }
    __syncwarp();

    // ---- P @ V: 4 rows x d-chunk float4 per thread ----
#pragma unroll
    for (int j = 0; j < 4; j++) {
      const ull ff = pack2(fac[j], fac[j]);
      o2[j][0] = fmul2(o2[j][0], ff);
      o2[j][1] = fmul2(o2[j][1], ff);
    }
#pragma unroll
    for (int tt = 0; tt < KBLK; tt += 4) {
      float4 p4[4];
#pragma unroll
      for (int j = 0; j < 4; j++)
        p4[j] = *(const float4*)&ps[(4 * rg + j) * 36 + tt];
#pragma unroll
      for (int u = 0; u < 4; u++) {
        const ulonglong2 vv = *(const ulonglong2*)&vst[(tt + u) * 132 + 4 * kg];
#pragma unroll
        for (int j = 0; j < 4; j++) {
          const float p = (&p4[j].x)[u];
          const ull pp = pack2(p, p);
          ffma2(o2[j][0], pp, vv.x);
          ffma2(o2[j][1], pp, vv.y);
        }
      }
    }
    __syncthreads();
  }

  const int base = (bh * NSPLIT + split) * 16;
#pragma unroll
  for (int j = 0; j < 4; j++) {
    const int r = 4 * rg + j;
    const float2 lo = unpack2(o2[j][0]);
    const float2 hi = unpack2(o2[j][1]);
    float4 o = make_float4(lo.x, lo.y, hi.x, hi.y);
    *(float4*)&g_Op[(base + r) * cD + 4 * kg] = o;
  }
  if (kg == 0) {
#pragma unroll
    for (int j = 0; j < 4; j++) {
      g_Ms[base + 4 * rg + j] = mrun[j];
      g_Ls[base + 4 * rg + j] = lrun[j];
    }
  }
  (void)tta; (void)dva;
}

// ---------------------------------------------------------------------------
// Combine KV splits -> attention output buffer.
// ---------------------------------------------------------------------------
__global__ __launch_bounds__(256) void combine_kernel() {
  const int bh = blockIdx.x, tid = threadIdx.x;
  const int r = tid >> 4;
  const int dq = (tid & 15) * 8;
  const int b = bh >> 3, h = bh & 7;
  const int base = bh * NSPLIT;
  float m[NSPLIT], l[NSPLIT];
  float mstar = -1e30f;
#pragma unroll
  for (int i = 0; i < NSPLIT; i++) {
    m[i] = g_Ms[(base + i) * 16 + r];
    l[i] = g_Ls[(base + i) * 16 + r];
    mstar = fmaxf(mstar, m[i]);
  }
  float w[NSPLIT];
  float L = 0.f;
#pragma unroll
  for (int i = 0; i < NSPLIT; i++) {
    w[i] = __expf(m[i] - mstar);
    L = fmaf(w[i], l[i], L);
  }
  const float inv = 1.f / L;
  const int s = r >> 2, g = r & 3;
  float* dst = &g_ao[((b * cS + s) * cHQ + (h * 4 + g)) * cD + dq];
#pragma unroll
  for (int c2 = 0; c2 < 2; c2++) {
    float4 a = make_float4(0.f, 0.f, 0.f, 0.f);
#pragma unroll
    for (int i = 0; i < NSPLIT; i++) {
      const float4 ov = *(const float4*)&g_Op[((base + i) * 16 + r) * cD + dq + 4 * c2];
      a.x = fmaf(w[i], ov.x, a.x);
      a.y = fmaf(w[i], ov.y, a.y);
      a.z = fmaf(w[i], ov.z, a.z);
      a.w = fmaf(w[i], ov.w, a.w);
    }
    a.x *= inv; a.y *= inv; a.z *= inv; a.w *= inv;
    *(float4*)&dst[4 * c2] = a;
  }
}

// ---------------------------------------------------------------------------
__global__ __launch_bounds__(256) void sum_out_kernel(float* __restrict__ out) {
  const int i = blockIdx.x * 256 + threadIdx.x;
  if (i < cM * cNQ)
    out[i] = g_outp[0][i] + g_outp[1][i] + g_outp[2][i] + g_outp[3][i];
}

// ---------------------------------------------------------------------------
extern "C" void kernel_launch(void* const* d_in, const int* in_sizes, int n_in,
                              void* d_out, int out_size) {
  const float* x = (const float*)d_in[0];
  const float* wq = (const float*)d_in[1];
  const float* wk = (const float*)d_in[2];
  const float* wv = (const float*)d_in[3];
  const float* wo = (const float*)d_in[4];
  const float* cosb = (const float*)d_in[5];
  const float* sinb = (const float*)d_in[6];
  const float* kc = (const float*)d_in[7];
  const float* vc = (const float*)d_in[8];
  const int* pl = (const int*)d_in[9];
  float* out = (float*)d_out;

  float *qkvp, *aop, *outp;
  cudaGetSymbolAddress((void**)&qkvp, g_qkvp);
  cudaGetSymbolAddress((void**)&aop, g_ao);
  cudaGetSymbolAddress((void**)&outp, g_outp);

  // Combined QKV projection (split-K partials): 64 q-tiles + 16 k + 16 v
  gemm_f2_kernel<<<dim3(96, KSPLIT), 128>>>(x, wq, wk, wv, qkvp, 1);
  // reduce + RoPE
  rope_kernel<<<(cM * cNTOT + 255) / 256, 256>>>(cosb, sinb, pl);
  // flash-decoding attention (cp.async pipelined)
  cudaFuncSetAttribute(attn_kernel, cudaFuncAttributeMaxDynamicSharedMemorySize, ATTN_SMEM);
  attn_kernel<<<dim3(cB * cHKV, NSPLIT), 128, ATTN_SMEM>>>(kc, vc, pl);
  combine_kernel<<<cB * cHKV, 256>>>();
  // output projection
  gemm_f2_kernel<<<dim3(64, KSPLIT), 128>>>(aop, wo, wo, wo, outp, 0);
  sum_out_kernel<<<(cM * cNQ + 255) / 256, 256>>>(out);
}